// round 2
// baseline (speedup 1.0000x reference)
#include <cuda_runtime.h>
#include <math.h>

#define A_COUNT 1024
#define DFEAT   128
#define NTOTAL  524288

// eps = 1e-4 / D
#define EPS (7.8125e-7f)

// rows per warp
#define RPW 8
#define BLOCK_THREADS 256
#define WARPS_PER_BLOCK (BLOCK_THREADS / 32)
#define ROWS_PER_BLOCK (WARPS_PER_BLOCK * RPW)   // 64

// Zero at module load; finalize_kernel resets it after reading, so every
// graph replay (and the first correctness call) sees zeros. No init kernel.
__device__ float g_per_anchor[A_COUNT];

__global__ __launch_bounds__(BLOCK_THREADS)
void dist_kernel(const float* __restrict__ anchors,
                 const float* __restrict__ X,
                 const int*   __restrict__ seg) {
    const int lane = threadIdx.x & 31;
    const int warp = threadIdx.x >> 5;
    const int base = (blockIdx.x * WARPS_PER_BLOCK + warp) * RPW;
    if (base >= NTOTAL) return;

    const float4* __restrict__ X4 = reinterpret_cast<const float4*>(X);
    const float4* __restrict__ A4 = reinterpret_cast<const float4*>(anchors);

    // Hoist all segment ids for this warp's 8 rows (uniform broadcast loads).
    int s[RPW];
    #pragma unroll
    for (int r = 0; r < RPW; r++) s[r] = __ldg(&seg[base + r]);

    int cur_seg = s[0];
    float4 a = A4[(size_t)cur_seg * (DFEAT / 4) + lane];

    // 3-deep row pipeline: keep >=3 streaming LDG.128 in flight per warp.
    float4 xbuf[3];
    xbuf[0] = __ldcs(&X4[(size_t)(base + 0) * (DFEAT / 4) + lane]);
    xbuf[1] = __ldcs(&X4[(size_t)(base + 1) * (DFEAT / 4) + lane]);
    xbuf[2] = __ldcs(&X4[(size_t)(base + 2) * (DFEAT / 4) + lane]);

    float acc = 0.0f;   // lane 0's running per-segment sum

    #pragma unroll
    for (int r = 0; r < RPW; r++) {
        float4 x = xbuf[r % 3];

        // Refill pipeline slot before consuming.
        if (r + 3 < RPW)
            xbuf[r % 3] = __ldcs(&X4[(size_t)(base + r + 3) * (DFEAT / 4) + lane]);

        float d0 = x.x - a.x;
        float d1 = x.y - a.y;
        float d2 = x.z - a.z;
        float d3 = x.w - a.w;
        float ss = d0 * d0 + d1 * d1 + d2 * d2 + d3 * d3;

        #pragma unroll
        for (int off = 16; off; off >>= 1)
            ss += __shfl_xor_sync(0xffffffffu, ss, off);

        if (lane == 0) acc += sqrtf(ss + EPS);

        if (r + 1 < RPW) {
            if (s[r + 1] != cur_seg) {
                // Segment boundary (warp-uniform): flush and reload anchor.
                if (lane == 0) {
                    atomicAdd(&g_per_anchor[cur_seg], acc);
                    acc = 0.0f;
                }
                cur_seg = s[r + 1];
                a = A4[(size_t)cur_seg * (DFEAT / 4) + lane];
            }
        }
    }

    if (lane == 0) atomicAdd(&g_per_anchor[cur_seg], acc);
}

__global__ __launch_bounds__(1024)
void finalize_kernel(float* __restrict__ out) {
    __shared__ float sdata[32];
    const int tid = threadIdx.x;     // 1024 threads, one per anchor

    float pa = g_per_anchor[tid];
    g_per_anchor[tid] = 0.0f;        // reset for the next graph replay

    float v = log1pf(pa);

    #pragma unroll
    for (int off = 16; off; off >>= 1)
        v += __shfl_xor_sync(0xffffffffu, v, off);

    if ((tid & 31) == 0) sdata[tid >> 5] = v;
    __syncthreads();

    if (tid < 32) {
        float w = sdata[tid];
        #pragma unroll
        for (int off = 16; off; off >>= 1)
            w += __shfl_xor_sync(0xffffffffu, w, off);
        if (tid == 0) out[0] = w / (float)NTOTAL;
    }
}

extern "C" void kernel_launch(void* const* d_in, const int* in_sizes, int n_in,
                              void* d_out, int out_size) {
    const float* anchors = (const float*)d_in[0];   // [A, D]
    const float* Xn_flat = (const float*)d_in[1];   // [TOTAL, D]
    const int*   seg     = (const int*)d_in[2];     // [TOTAL]
    float* out = (float*)d_out;

    const int grid = NTOTAL / ROWS_PER_BLOCK;       // 8192 blocks
    dist_kernel<<<grid, BLOCK_THREADS>>>(anchors, Xn_flat, seg);

    finalize_kernel<<<1, 1024>>>(out);
}

// round 3
// speedup vs baseline: 1.1514x; 1.1514x over previous
#include <cuda_runtime.h>
#include <math.h>

#define A_COUNT 1024
#define DFEAT   128
#define NTOTAL  524288

// eps = 1e-4 / D
#define EPS (7.8125e-7f)

// rows per warp
#define RPW 8
#define BLOCK_THREADS 256
#define WARPS_PER_BLOCK (BLOCK_THREADS / 32)
#define ROWS_PER_BLOCK (WARPS_PER_BLOCK * RPW)   // 64

// Zero at module load; finalize_kernel resets it after reading, so every
// graph replay (and the first correctness call) sees zeros. No init kernel.
__device__ float g_per_anchor[A_COUNT];

__global__ __launch_bounds__(BLOCK_THREADS)
void dist_kernel(const float* __restrict__ anchors,
                 const float* __restrict__ X,
                 const int*   __restrict__ seg) {
    const int lane = threadIdx.x & 31;
    const int warp = threadIdx.x >> 5;
    const int base = (blockIdx.x * WARPS_PER_BLOCK + warp) * RPW;
    if (base >= NTOTAL) return;

    // Per-lane float4 covers the whole 128-float row: lane*4 .. lane*4+3.
    const float4* __restrict__ X4 = reinterpret_cast<const float4*>(X);
    const float4* __restrict__ A4 = reinterpret_cast<const float4*>(anchors);

    int   cur_seg = seg[base];
    float4 a = A4[(size_t)cur_seg * (DFEAT / 4) + lane];
    float4 x = X4[(size_t)base * (DFEAT / 4) + lane];

    float acc = 0.0f;   // only lane 0's value matters

    #pragma unroll
    for (int r = 0; r < RPW; r++) {
        const int row = base + r;

        // Prefetch next row's data before consuming current (MLP>=2 per warp,
        // interleaved — keep MLP_p1 low to avoid L1tex-queue spread).
        float4 x_next;
        int    s_next = cur_seg;
        if (r + 1 < RPW) {
            s_next = seg[row + 1];
            x_next = X4[(size_t)(row + 1) * (DFEAT / 4) + lane];
        }

        float d0 = x.x - a.x;
        float d1 = x.y - a.y;
        float d2 = x.z - a.z;
        float d3 = x.w - a.w;
        float ss = d0 * d0 + d1 * d1 + d2 * d2 + d3 * d3;

        #pragma unroll
        for (int off = 16; off; off >>= 1)
            ss += __shfl_xor_sync(0xffffffffu, ss, off);

        if (lane == 0) acc += sqrtf(ss + EPS);

        if (r + 1 < RPW) {
            if (s_next != cur_seg) {
                // Segment boundary (warp-uniform): flush and reload anchor.
                if (lane == 0) {
                    atomicAdd(&g_per_anchor[cur_seg], acc);
                    acc = 0.0f;
                }
                cur_seg = s_next;
                a = A4[(size_t)cur_seg * (DFEAT / 4) + lane];
            }
            x = x_next;
        }
    }

    if (lane == 0) atomicAdd(&g_per_anchor[cur_seg], acc);
}

__global__ __launch_bounds__(1024)
void finalize_kernel(float* __restrict__ out) {
    __shared__ float sdata[32];
    const int tid = threadIdx.x;     // 1024 threads, one per anchor

    float pa = g_per_anchor[tid];
    g_per_anchor[tid] = 0.0f;        // reset for the next graph replay

    float v = log1pf(pa);

    #pragma unroll
    for (int off = 16; off; off >>= 1)
        v += __shfl_xor_sync(0xffffffffu, v, off);

    if ((tid & 31) == 0) sdata[tid >> 5] = v;
    __syncthreads();

    if (tid < 32) {
        float w = sdata[tid];
        #pragma unroll
        for (int off = 16; off; off >>= 1)
            w += __shfl_xor_sync(0xffffffffu, w, off);
        if (tid == 0) out[0] = w / (float)NTOTAL;
    }
}

extern "C" void kernel_launch(void* const* d_in, const int* in_sizes, int n_in,
                              void* d_out, int out_size) {
    const float* anchors = (const float*)d_in[0];   // [A, D]
    const float* Xn_flat = (const float*)d_in[1];   // [TOTAL, D]
    const int*   seg     = (const int*)d_in[2];     // [TOTAL]
    float* out = (float*)d_out;

    const int grid = NTOTAL / ROWS_PER_BLOCK;       // 8192 blocks
    dist_kernel<<<grid, BLOCK_THREADS>>>(anchors, Xn_flat, seg);

    finalize_kernel<<<1, 1024>>>(out);
}